// round 9
// baseline (speedup 1.0000x reference)
#include <cuda_runtime.h>
#include <cuda_bf16.h>
#include <mma.h>
#include <cstdint>

using namespace nvcuda;

// ---------------- device scratch (static; no allocations) ----------------
__device__ __nv_bfloat16 g_xln  [2L*16384*1024];
__device__ __nv_bfloat16 g_wqkv [2L*3*1024*1024];
__device__ __nv_bfloat16 g_wo   [2L*1024*1024];
__device__ __nv_bfloat16 g_w1   [2L*1024*4096];
__device__ __nv_bfloat16 g_w2   [2L*4096*1024];
__device__ __nv_bfloat16 g_qkv  [2L*3*16384*1024];
__device__ float         g_Smat [1024L*256*256];
__device__ __nv_bfloat16 g_Pmat [1024L*256*256];
__device__ __nv_bfloat16 g_Omat [2L*16384*1024];
__device__ float         g_att  [2L*16384*1024];
__device__ __nv_bfloat16 g_attln[2L*16384*1024];
__device__ __nv_bfloat16 g_hid  [2L*16384*4096];

// ---------------- helpers ----------------
__device__ __forceinline__ uint32_t smem_u32(const void* p) {
    uint32_t a;
    asm("{ .reg .u64 t; cvta.to.shared.u64 t, %1; cvt.u32.u64 %0, t; }" : "=r"(a) : "l"(p));
    return a;
}
__device__ __forceinline__ void cpa16(uint32_t d, const void* s) {
    asm volatile("cp.async.cg.shared.global [%0], [%1], 16;" :: "r"(d), "l"(s));
}
#define CP_COMMIT() asm volatile("cp.async.commit_group;" ::: "memory")

// ---------------- fused convert (8 regions, one launch) ----------------
struct CvtP {
    const float* s[8];
    __nv_bfloat16* d[8];
    long n[8];
};
__global__ void cvt8_k(CvtP p) {
    int reg = blockIdx.y;
    long i = (long)blockIdx.x * 1024 + threadIdx.x;
    const float* s = p.s[reg];
    __nv_bfloat16* d = p.d[reg];
    long n = p.n[reg];
#pragma unroll
    for (int it = 0; it < 4; ++it) {
        long j = i + (long)it * 256;
        if (j < n) d[j] = __float2bfloat16(s[j]);
    }
}

// ---------------- fused dual LayerNorm ----------------
__global__ void ln2_k(const float* __restrict__ x0, __nv_bfloat16* __restrict__ y0,
                      const float* __restrict__ g0, const float* __restrict__ b0,
                      const float* __restrict__ x1, __nv_bfloat16* __restrict__ y1,
                      const float* __restrict__ g1, const float* __restrict__ b1) {
    const float* x = blockIdx.y ? x1 : x0;
    __nv_bfloat16* y = blockIdx.y ? y1 : y0;
    const float* gam = blockIdx.y ? g1 : g0;
    const float* bet = blockIdx.y ? b1 : b0;
    long row = blockIdx.x;
    const float* xr = x + row * 1024;
    int tid = threadIdx.x;
    float v[4]; float s = 0.f, s2 = 0.f;
#pragma unroll
    for (int i = 0; i < 4; i++) { float t = xr[tid + i*256]; v[i] = t; s += t; s2 += t*t; }
#pragma unroll
    for (int o = 16; o; o >>= 1) {
        s  += __shfl_xor_sync(0xffffffffu, s,  o);
        s2 += __shfl_xor_sync(0xffffffffu, s2, o);
    }
    __shared__ float sh[2][8];
    if ((tid & 31) == 0) { sh[0][tid>>5] = s; sh[1][tid>>5] = s2; }
    __syncthreads();
    float S = 0.f, S2 = 0.f;
#pragma unroll
    for (int w = 0; w < 8; w++) { S += sh[0][w]; S2 += sh[1][w]; }
    float m   = S  * (1.f/1024.f);
    float var = S2 * (1.f/1024.f) - m*m;
    float inv = rsqrtf(var + 1e-5f);
#pragma unroll
    for (int i = 0; i < 4; i++) {
        int c = tid + i*256;
        y[row*1024 + c] = __float2bfloat16((v[i]-m)*inv*gam[c] + bet[c]);
    }
}

__global__ void softmax_k(const float* __restrict__ S, __nv_bfloat16* __restrict__ P) {
    long row = (long)blockIdx.x * 8 + (threadIdx.x >> 5);
    int lane = threadIdx.x & 31;
    const float* sr = S + row * 256;
    float v[8]; float m = -1e30f;
#pragma unroll
    for (int e = 0; e < 8; e++) { v[e] = sr[e*32 + lane]; m = fmaxf(m, v[e]); }
#pragma unroll
    for (int o = 16; o; o >>= 1) m = fmaxf(m, __shfl_xor_sync(0xffffffffu, m, o));
    float s = 0.f;
#pragma unroll
    for (int e = 0; e < 8; e++) { v[e] = __expf(v[e] - m); s += v[e]; }
#pragma unroll
    for (int o = 16; o; o >>= 1) s += __shfl_xor_sync(0xffffffffu, s, o);
    float inv = 1.f / s;
#pragma unroll
    for (int e = 0; e < 8; e++)
        P[row*256 + e*32 + lane] = __float2bfloat16(v[e] * inv);
}

// ---------------- GEMM params ----------------
struct GP {
    const __nv_bfloat16* A;
    const __nv_bfloat16* B;
    long lda, ldb, ldc;
    long sAb, sAh, sBb, sBh, sCb, sCh;
    int  Hh;
    int  K;
    void* C;
    const float* bias;
    const float* resid; long ldr;
    const float* coeffs; int ci0, ci1;
    float alpha;
};

// ---------------- pipelined wmma GEMM: 128 threads, warp tile 64x64 ----------------
// EPI: 0 = bf16 store (+opt bias), 1 = fp32 store * alpha,
//      3 = fp32 store: c_res*resid + c_out*(acc+bias), 4 = bf16 gelu(acc+bias)
static const int BM = 128, BN = 128, BK = 32;
static const int STG = 4;
static const int LDA_S  = BK + 8;        // 40 elems = 80 B
static const int LDB_NN = BN + 8;        // 136 elems = 272 B
static const int LDB_NT = BK + 8;        // 40
static const int EPLD   = 20;
static const int A_STG_B   = BM * LDA_S * 2;      // 10240 B
static const int B_STG_NN  = BK * LDB_NN * 2;     // 8704 B
static const int B_STG_NT  = BN * LDB_NT * 2;     // 10240 B
static const int SMEM_NN   = STG * (A_STG_B + B_STG_NN);  // 75776
static const int SMEM_NT   = STG * (A_STG_B + B_STG_NT);  // 81920

template <int EPI, bool TB>
__global__ void __launch_bounds__(128, 2) gemm_k(GP p) {
    extern __shared__ char dsm[];
    const int tid  = threadIdx.x;
    const int warp = tid >> 5, lane = tid & 31;
    const int wm = warp >> 1, wn = warp & 1;   // 2x2 warp grid, 64x64 warp tile

    const int z  = blockIdx.z;
    const int bb = z / p.Hh, hh = z - bb * p.Hh;
    const __nv_bfloat16* Ab = p.A + (long)bb * p.sAb + (long)hh * p.sAh;
    const __nv_bfloat16* Bb = p.B + (long)bb * p.sBb + (long)hh * p.sBh;
    const long coff = (long)bb * p.sCb + (long)hh * p.sCh;

    const int row0 = blockIdx.y * BM;
    const int col0 = blockIdx.x * BN;
    const long lda = p.lda, ldb = p.ldb;

    const uint32_t asb = smem_u32(dsm);
    const uint32_t bsb = asb + STG * A_STG_B;
    __nv_bfloat16* As = (__nv_bfloat16*)dsm;
    __nv_bfloat16* Bs = (__nv_bfloat16*)(dsm + STG * A_STG_B);

    auto load_stage = [&](int slot, int k0) {
        uint32_t ab = asb + slot * A_STG_B;
#pragma unroll
        for (int it = 0; it < 4; ++it) {
            int id = tid + it*128;
            int r = id >> 2, c = id & 3;
            cpa16(ab + r*80 + c*16, Ab + (long)(row0 + r)*lda + k0 + c*8);
        }
        if (!TB) {
            uint32_t bbp = bsb + slot * B_STG_NN;
#pragma unroll
            for (int it = 0; it < 4; ++it) {
                int id = tid + it*128;
                int r = id >> 4, c = id & 15;
                cpa16(bbp + r*272 + c*16, Bb + (long)(k0 + r)*ldb + col0 + c*8);
            }
        } else {
            uint32_t bbp = bsb + slot * B_STG_NT;
#pragma unroll
            for (int it = 0; it < 4; ++it) {
                int id = tid + it*128;
                int r = id >> 2, c = id & 3;
                cpa16(bbp + r*80 + c*16, Bb + (long)(col0 + r)*ldb + k0 + c*8);
            }
        }
    };

    wmma::fragment<wmma::accumulator, 16, 16, 16, float> acc[4][4];
#pragma unroll
    for (int i = 0; i < 4; i++)
#pragma unroll
        for (int j = 0; j < 4; j++) wmma::fill_fragment(acc[i][j], 0.f);

    const int kiters = p.K >> 5;

#pragma unroll
    for (int s = 0; s < STG-1; ++s) {
        if (s < kiters) load_stage(s, s * BK);
        CP_COMMIT();
    }

    for (int k = 0; k < kiters; ++k) {
        asm volatile("cp.async.wait_group %0;" :: "n"(STG-2));
        __syncthreads();
        // prefetch into the slot drained two iterations ago (safe after the sync)
        int pf = k + STG - 1;
        if (pf < kiters) load_stage(pf % STG, pf * BK);
        CP_COMMIT();

        int slot = k % STG;
        __nv_bfloat16* Asl = As + slot * (BM * LDA_S);
#pragma unroll
        for (int kk = 0; kk < BK; kk += 16) {
            wmma::fragment<wmma::matrix_a, 16, 16, 16, __nv_bfloat16, wmma::row_major> fa[4];
#pragma unroll
            for (int mi = 0; mi < 4; ++mi)
                wmma::load_matrix_sync(fa[mi], &Asl[(wm*64 + mi*16)*LDA_S + kk], LDA_S);
            if (!TB) {
                __nv_bfloat16* Bsl = Bs + slot * (BK * LDB_NN);
                wmma::fragment<wmma::matrix_b, 16, 16, 16, __nv_bfloat16, wmma::row_major> fb[4];
#pragma unroll
                for (int ni = 0; ni < 4; ++ni)
                    wmma::load_matrix_sync(fb[ni], &Bsl[kk*LDB_NN + wn*64 + ni*16], LDB_NN);
#pragma unroll
                for (int mi = 0; mi < 4; ++mi)
#pragma unroll
                    for (int ni = 0; ni < 4; ++ni)
                        wmma::mma_sync(acc[mi][ni], fa[mi], fb[ni], acc[mi][ni]);
            } else {
                __nv_bfloat16* Bsl = Bs + slot * (BN * LDB_NT);
                wmma::fragment<wmma::matrix_b, 16, 16, 16, __nv_bfloat16, wmma::col_major> fb[4];
#pragma unroll
                for (int ni = 0; ni < 4; ++ni)
                    wmma::load_matrix_sync(fb[ni], &Bsl[(wn*64 + ni*16)*LDB_NT + kk], LDB_NT);
#pragma unroll
                for (int mi = 0; mi < 4; ++mi)
#pragma unroll
                    for (int ni = 0; ni < 4; ++ni)
                        wmma::mma_sync(acc[mi][ni], fa[mi], fb[ni], acc[mi][ni]);
            }
        }
        __syncthreads();
    }

    // ---------------- epilogue (reuse dsm as staging) ----------------
    float c_res = 0.f, c_out = 0.f;
    if (EPI == 3) { c_res = p.coeffs[p.ci0]; c_out = p.coeffs[p.ci1]; }
    float* ep = (float*)dsm;
    float* eptr = &ep[warp * 16 * EPLD];
#pragma unroll
    for (int mi = 0; mi < 4; ++mi) {
#pragma unroll
        for (int ni = 0; ni < 4; ++ni) {
            wmma::store_matrix_sync(eptr, acc[mi][ni], EPLD, wmma::mem_row_major);
            __syncwarp();
            int r0 = row0 + wm*64 + mi*16;
            int c0 = col0 + wn*64 + ni*16;
#pragma unroll
            for (int e = 0; e < 8; ++e) {
                int i = e*32 + lane;
                int r = i >> 4, c = i & 15;
                float v = eptr[r*EPLD + c];
                long gr = r0 + r, gc = c0 + c;
                long cidx = coff + gr*p.ldc + gc;
                if (EPI == 0) {
                    if (p.bias) v += p.bias[gc];
                    ((__nv_bfloat16*)p.C)[cidx] = __float2bfloat16(v);
                } else if (EPI == 1) {
                    ((float*)p.C)[cidx] = v * p.alpha;
                } else if (EPI == 3) {
                    v += p.bias[gc];
                    ((float*)p.C)[cidx] = c_res * p.resid[gr*p.ldr + gc] + c_out * v;
                } else if (EPI == 4) {
                    v += p.bias[gc];
                    float gl = 0.5f * v * (1.f + erff(v * 0.70710678118654752f));
                    ((__nv_bfloat16*)p.C)[cidx] = __float2bfloat16(gl);
                }
            }
            __syncwarp();
        }
    }
}

// ---------------- host orchestration ----------------
extern "C" void kernel_launch(void* const* d_in, const int* in_sizes, int n_in,
                              void* d_out, int out_size) {
    (void)in_sizes; (void)n_in; (void)out_size;
    const float* rgb    = (const float*)d_in[0];
    const float* irp    = (const float*)d_in[1];
    const float* ln1g   = (const float*)d_in[2];
    const float* ln1b   = (const float*)d_in[3];
    const float* ln2g   = (const float*)d_in[4];
    const float* ln2b   = (const float*)d_in[5];
    const float* Wqkv_v = (const float*)d_in[6];
    const float* bqkv_v = (const float*)d_in[7];
    const float* Wqkv_i = (const float*)d_in[8];
    const float* bqkv_i = (const float*)d_in[9];
    const float* Wo_v   = (const float*)d_in[10];
    const float* bo_v   = (const float*)d_in[11];
    const float* Wo_i   = (const float*)d_in[12];
    const float* bo_i   = (const float*)d_in[13];
    const float* blng   = (const float*)d_in[14];
    const float* blnb   = (const float*)d_in[15];
    const float* W1_v   = (const float*)d_in[16];
    const float* b1_v   = (const float*)d_in[17];
    const float* W2_v   = (const float*)d_in[18];
    const float* b2_v   = (const float*)d_in[19];
    const float* W1_i   = (const float*)d_in[20];
    const float* b1_i   = (const float*)d_in[21];
    const float* W2_i   = (const float*)d_in[22];
    const float* b2_i   = (const float*)d_in[23];
    const float* coef   = (const float*)d_in[24];
    float* out = (float*)d_out;

    __nv_bfloat16 *xln, *wqkv, *wo, *w1, *w2, *qkv, *Pb, *Ob, *attln, *hb;
    float *Sb, *attb;
    cudaGetSymbolAddress((void**)&xln,   g_xln);
    cudaGetSymbolAddress((void**)&wqkv,  g_wqkv);
    cudaGetSymbolAddress((void**)&wo,    g_wo);
    cudaGetSymbolAddress((void**)&w1,    g_w1);
    cudaGetSymbolAddress((void**)&w2,    g_w2);
    cudaGetSymbolAddress((void**)&qkv,   g_qkv);
    cudaGetSymbolAddress((void**)&Sb,    g_Smat);
    cudaGetSymbolAddress((void**)&Pb,    g_Pmat);
    cudaGetSymbolAddress((void**)&Ob,    g_Omat);
    cudaGetSymbolAddress((void**)&attb,  g_att);
    cudaGetSymbolAddress((void**)&attln, g_attln);
    cudaGetSymbolAddress((void**)&hb,    g_hid);

    cudaFuncSetAttribute(gemm_k<0, false>, cudaFuncAttributeMaxDynamicSharedMemorySize, SMEM_NN);
    cudaFuncSetAttribute(gemm_k<3, false>, cudaFuncAttributeMaxDynamicSharedMemorySize, SMEM_NN);
    cudaFuncSetAttribute(gemm_k<4, false>, cudaFuncAttributeMaxDynamicSharedMemorySize, SMEM_NN);
    cudaFuncSetAttribute(gemm_k<1, true>,  cudaFuncAttributeMaxDynamicSharedMemorySize, SMEM_NT);

    // weights -> bf16 (one launch, 8 regions)
    {
        CvtP cp{};
        cp.s[0] = Wqkv_v; cp.d[0] = wqkv;            cp.n[0] = 3145728L;
        cp.s[1] = Wqkv_i; cp.d[1] = wqkv + 3145728L; cp.n[1] = 3145728L;
        cp.s[2] = Wo_v;   cp.d[2] = wo;              cp.n[2] = 1048576L;
        cp.s[3] = Wo_i;   cp.d[3] = wo + 1048576L;   cp.n[3] = 1048576L;
        cp.s[4] = W1_v;   cp.d[4] = w1;              cp.n[4] = 4194304L;
        cp.s[5] = W1_i;   cp.d[5] = w1 + 4194304L;   cp.n[5] = 4194304L;
        cp.s[6] = W2_v;   cp.d[6] = w2;              cp.n[6] = 4194304L;
        cp.s[7] = W2_i;   cp.d[7] = w2 + 4194304L;   cp.n[7] = 4194304L;
        cvt8_k<<<dim3(4096, 8), 256>>>(cp);
    }

    // input LayerNorms (one launch)
    ln2_k<<<dim3(16384, 2), 256>>>(rgb, xln, ln1g, ln1b,
                                   irp, xln + 16777216L, ln2g, ln2b);

    // QKV projections (6 GEMMs, M=16384 N=1024 K=1024) — launch #6 is profiled
    for (int s = 0; s < 2; s++) {
        for (int t = 0; t < 3; t++) {
            GP p{};
            p.A = xln + (long)s * 16777216L;                 p.lda = 1024;
            p.B = wqkv + ((long)s*3 + t) * 1048576L;         p.ldb = 1024;
            p.C = qkv + ((long)s*3 + t) * 16777216L;         p.ldc = 1024;
            p.bias = (s == 0 ? bqkv_v : bqkv_i) + t * 1024;
            p.Hh = 1; p.K = 1024; p.coeffs = coef;
            gemm_k<0, false><<<dim3(8, 128, 1), 128, SMEM_NN>>>(p);
        }
    }

    // scores S = Q @ K^T * scale  (batched over b,h)
    for (int dir = 0; dir < 2; ++dir) {
        int qs = (dir == 0) ? 1 : 0;
        int ks = (dir == 0) ? 0 : 1;
        GP p{};
        p.A = qkv + ((long)qs*3 + 0) * 16777216L;  p.lda = 1024; p.sAb = 262144; p.sAh = 128;
        p.B = qkv + ((long)ks*3 + 1) * 16777216L;  p.ldb = 1024; p.sBb = 262144; p.sBh = 128;
        p.C = Sb + (long)dir * 33554432L;          p.ldc = 256;  p.sCb = 524288; p.sCh = 65536;
        p.Hh = 8; p.K = 128; p.alpha = 0.08838834764831845f; p.coeffs = coef;
        gemm_k<1, true><<<dim3(2, 2, 512), 128, SMEM_NT>>>(p);
    }

    softmax_k<<<32768, 256>>>(Sb, Pb);

    // O = P @ V (batched), merged layout
    for (int dir = 0; dir < 2; ++dir) {
        int ks = (dir == 0) ? 0 : 1;
        GP p{};
        p.A = Pb + (long)dir * 33554432L;          p.lda = 256;  p.sAb = 524288; p.sAh = 65536;
        p.B = qkv + ((long)ks*3 + 2) * 16777216L;  p.ldb = 1024; p.sBb = 262144; p.sBh = 128;
        p.C = Ob + (long)dir * 16777216L;          p.ldc = 1024; p.sCb = 262144; p.sCh = 128;
        p.bias = nullptr; p.Hh = 8; p.K = 256; p.coeffs = coef;
        gemm_k<0, false><<<dim3(1, 2, 512), 128, SMEM_NN>>>(p);
    }

    // output projection + residual
    for (int dir = 0; dir < 2; ++dir) {
        GP p{};
        p.A = Ob + (long)dir * 16777216L;   p.lda = 1024;
        p.B = wo + (long)dir * 1048576L;    p.ldb = 1024;
        p.C = attb + (long)dir * 16777216L; p.ldc = 1024;
        p.bias = (dir == 0) ? bo_v : bo_i;
        p.resid = (dir == 0) ? rgb : irp;   p.ldr = 1024;
        p.coeffs = coef; p.ci0 = 2*dir; p.ci1 = 2*dir + 1;
        p.Hh = 1; p.K = 1024;
        gemm_k<3, false><<<dim3(8, 128, 1), 128, SMEM_NN>>>(p);
    }

    // block LayerNorm (one launch, shared gamma/beta)
    ln2_k<<<dim3(16384, 2), 256>>>(attb, attln, blng, blnb,
                                   attb + 16777216L, attln + 16777216L, blng, blnb);

    // MLP layer 1 + exact GELU (M=16384 N=4096 K=1024)
    for (int s = 0; s < 2; s++) {
        GP p{};
        p.A = attln + (long)s * 16777216L;  p.lda = 1024;
        p.B = w1 + (long)s * 4194304L;      p.ldb = 4096;
        p.C = hb + (long)s * 67108864L;     p.ldc = 4096;
        p.bias = (s == 0) ? b1_v : b1_i;
        p.Hh = 1; p.K = 1024; p.coeffs = coef;
        gemm_k<4, false><<<dim3(32, 128, 1), 128, SMEM_NN>>>(p);
    }

    // MLP layer 2 + final combine -> d_out (M=16384 N=1024 K=4096)
    for (int s = 0; s < 2; s++) {
        GP p{};
        p.A = hb + (long)s * 67108864L;     p.lda = 4096;
        p.B = w2 + (long)s * 4194304L;      p.ldb = 1024;
        p.C = out + (long)s * 16777216L;    p.ldc = 1024;
        p.bias = (s == 0) ? b2_v : b2_i;
        p.resid = attb + (long)s * 16777216L; p.ldr = 1024;
        p.coeffs = coef; p.ci0 = 4 + 2*s; p.ci1 = 5 + 2*s;
        p.Hh = 1; p.K = 4096;
        gemm_k<3, false><<<dim3(8, 128, 1), 128, SMEM_NN>>>(p);
    }
}

// round 10
// speedup vs baseline: 1.1621x; 1.1621x over previous
#include <cuda_runtime.h>
#include <cuda_bf16.h>
#include <mma.h>
#include <cstdint>

using namespace nvcuda;

// ---------------- device scratch (static; no allocations) ----------------
__device__ __nv_bfloat16 g_xln  [2L*16384*1024];
__device__ __nv_bfloat16 g_wqkv [2L*3*1024*1024];
__device__ __nv_bfloat16 g_wo   [2L*1024*1024];
__device__ __nv_bfloat16 g_w1   [2L*1024*4096];
__device__ __nv_bfloat16 g_w2   [2L*4096*1024];
__device__ __nv_bfloat16 g_qkv  [2L*3*16384*1024];
__device__ float         g_Smat [1024L*256*256];
__device__ __nv_bfloat16 g_Pmat [1024L*256*256];
__device__ __nv_bfloat16 g_Omat [2L*16384*1024];
__device__ float         g_att  [2L*16384*1024];
__device__ __nv_bfloat16 g_attln[2L*16384*1024];
__device__ __nv_bfloat16 g_hid  [2L*16384*4096];

// ---------------- helpers ----------------
__device__ __forceinline__ uint32_t smem_u32(const void* p) {
    uint32_t a;
    asm("{ .reg .u64 t; cvta.to.shared.u64 t, %1; cvt.u32.u64 %0, t; }" : "=r"(a) : "l"(p));
    return a;
}
__device__ __forceinline__ void cpa16(uint32_t d, const void* s) {
    asm volatile("cp.async.cg.shared.global [%0], [%1], 16;" :: "r"(d), "l"(s));
}
#define CP_COMMIT() asm volatile("cp.async.commit_group;" ::: "memory")

// ---------------- fused convert (8 regions, one launch) ----------------
struct CvtP {
    const float* s[8];
    __nv_bfloat16* d[8];
    long n[8];
};
__global__ void cvt8_k(CvtP p) {
    int reg = blockIdx.y;
    long i = (long)blockIdx.x * 1024 + threadIdx.x;
    const float* s = p.s[reg];
    __nv_bfloat16* d = p.d[reg];
    long n = p.n[reg];
#pragma unroll
    for (int it = 0; it < 4; ++it) {
        long j = i + (long)it * 256;
        if (j < n) d[j] = __float2bfloat16(s[j]);
    }
}

// ---------------- fused dual LayerNorm ----------------
__global__ void ln2_k(const float* __restrict__ x0, __nv_bfloat16* __restrict__ y0,
                      const float* __restrict__ g0, const float* __restrict__ b0,
                      const float* __restrict__ x1, __nv_bfloat16* __restrict__ y1,
                      const float* __restrict__ g1, const float* __restrict__ b1) {
    const float* x = blockIdx.y ? x1 : x0;
    __nv_bfloat16* y = blockIdx.y ? y1 : y0;
    const float* gam = blockIdx.y ? g1 : g0;
    const float* bet = blockIdx.y ? b1 : b0;
    long row = blockIdx.x;
    const float* xr = x + row * 1024;
    int tid = threadIdx.x;
    float v[4]; float s = 0.f, s2 = 0.f;
#pragma unroll
    for (int i = 0; i < 4; i++) { float t = xr[tid + i*256]; v[i] = t; s += t; s2 += t*t; }
#pragma unroll
    for (int o = 16; o; o >>= 1) {
        s  += __shfl_xor_sync(0xffffffffu, s,  o);
        s2 += __shfl_xor_sync(0xffffffffu, s2, o);
    }
    __shared__ float sh[2][8];
    if ((tid & 31) == 0) { sh[0][tid>>5] = s; sh[1][tid>>5] = s2; }
    __syncthreads();
    float S = 0.f, S2 = 0.f;
#pragma unroll
    for (int w = 0; w < 8; w++) { S += sh[0][w]; S2 += sh[1][w]; }
    float m   = S  * (1.f/1024.f);
    float var = S2 * (1.f/1024.f) - m*m;
    float inv = rsqrtf(var + 1e-5f);
#pragma unroll
    for (int i = 0; i < 4; i++) {
        int c = tid + i*256;
        y[row*1024 + c] = __float2bfloat16((v[i]-m)*inv*gam[c] + bet[c]);
    }
}

__global__ void softmax_k(const float* __restrict__ S, __nv_bfloat16* __restrict__ P) {
    long row = (long)blockIdx.x * 8 + (threadIdx.x >> 5);
    int lane = threadIdx.x & 31;
    const float* sr = S + row * 256;
    float v[8]; float m = -1e30f;
#pragma unroll
    for (int e = 0; e < 8; e++) { v[e] = sr[e*32 + lane]; m = fmaxf(m, v[e]); }
#pragma unroll
    for (int o = 16; o; o >>= 1) m = fmaxf(m, __shfl_xor_sync(0xffffffffu, m, o));
    float s = 0.f;
#pragma unroll
    for (int e = 0; e < 8; e++) { v[e] = __expf(v[e] - m); s += v[e]; }
#pragma unroll
    for (int o = 16; o; o >>= 1) s += __shfl_xor_sync(0xffffffffu, s, o);
    float inv = 1.f / s;
#pragma unroll
    for (int e = 0; e < 8; e++)
        P[row*256 + e*32 + lane] = __float2bfloat16(v[e] * inv);
}

// ---------------- GEMM params ----------------
struct GP {
    const __nv_bfloat16* A;
    const __nv_bfloat16* B;
    long lda, ldb, ldc;
    long sAb, sAh, sBb, sBh, sCb, sCh;
    int  Hh;
    int  K;
    void* C;
    const float* bias;
    const float* resid; long ldr;
    const float* coeffs; int ci0, ci1;
    float alpha;
};

// ---------------- pipelined wmma GEMM: 256 thr, BK=64, reg double-buffered ----------------
// EPI: 0 = bf16 store (+opt bias), 1 = fp32 store * alpha,
//      3 = fp32 store: c_res*resid + c_out*(acc+bias), 4 = bf16 gelu(acc+bias)
static const int BM = 128, BN = 128, BK = 64;
static const int STG = 3;
static const int LDA_S  = BK + 8;        // 72 elems = 144 B
static const int LDB_NN = BN + 8;        // 136 elems = 272 B
static const int LDB_NT = BK + 8;        // 72
static const int EPLD   = 20;
static const int A_STG_B   = BM * LDA_S * 2;      // 18432 B
static const int B_STG_NN  = BK * LDB_NN * 2;     // 17408 B
static const int B_STG_NT  = BN * LDB_NT * 2;     // 18432 B
static const int SMEM_NN   = STG * (A_STG_B + B_STG_NN);  // 107520
static const int SMEM_NT   = STG * (A_STG_B + B_STG_NT);  // 110592

template <int EPI, bool TB>
__global__ void __launch_bounds__(256) gemm_k(GP p) {
    extern __shared__ char dsm[];
    const int tid  = threadIdx.x;
    const int warp = tid >> 5, lane = tid & 31;
    const int wm = warp >> 2, wn = warp & 3;   // 2x4 warp grid, 64x32 warp tile

    const int z  = blockIdx.z;
    const int bb = z / p.Hh, hh = z - bb * p.Hh;
    const __nv_bfloat16* Ab = p.A + (long)bb * p.sAb + (long)hh * p.sAh;
    const __nv_bfloat16* Bb = p.B + (long)bb * p.sBb + (long)hh * p.sBh;
    const long coff = (long)bb * p.sCb + (long)hh * p.sCh;

    const int row0 = blockIdx.y * BM;
    const int col0 = blockIdx.x * BN;
    const long lda = p.lda, ldb = p.ldb;

    const uint32_t asb = smem_u32(dsm);
    const uint32_t bsb = asb + STG * A_STG_B;
    __nv_bfloat16* As = (__nv_bfloat16*)dsm;
    __nv_bfloat16* Bs = (__nv_bfloat16*)(dsm + STG * A_STG_B);

    auto load_stage = [&](int slot, int k0) {
        uint32_t ab = asb + slot * A_STG_B;
#pragma unroll
        for (int it = 0; it < 4; ++it) {
            int id = tid + it*256;
            int r = id >> 3, c = id & 7;
            cpa16(ab + r*144 + c*16, Ab + (long)(row0 + r)*lda + k0 + c*8);
        }
        if (!TB) {
            uint32_t bbp = bsb + slot * B_STG_NN;
#pragma unroll
            for (int it = 0; it < 4; ++it) {
                int id = tid + it*256;
                int r = id >> 4, c = id & 15;
                cpa16(bbp + r*272 + c*16, Bb + (long)(k0 + r)*ldb + col0 + c*8);
            }
        } else {
            uint32_t bbp = bsb + slot * B_STG_NT;
#pragma unroll
            for (int it = 0; it < 4; ++it) {
                int id = tid + it*256;
                int r = id >> 3, c = id & 7;
                cpa16(bbp + r*144 + c*16, Bb + (long)(col0 + r)*ldb + k0 + c*8);
            }
        }
    };

    wmma::fragment<wmma::accumulator, 16, 16, 16, float> acc[4][2];
#pragma unroll
    for (int i = 0; i < 4; i++)
#pragma unroll
        for (int j = 0; j < 2; j++) wmma::fill_fragment(acc[i][j], 0.f);

    wmma::fragment<wmma::matrix_a, 16, 16, 16, __nv_bfloat16, wmma::row_major> fa[2][4];
    wmma::fragment<wmma::matrix_b, 16, 16, 16, __nv_bfloat16, wmma::row_major> fbr[2][2];
    wmma::fragment<wmma::matrix_b, 16, 16, 16, __nv_bfloat16, wmma::col_major> fbc[2][2];

    const int kiters = p.K >> 6;

#pragma unroll
    for (int s = 0; s < STG-1; ++s) {
        if (s < kiters) load_stage(s, s * BK);
        CP_COMMIT();
    }

    for (int k = 0; k < kiters; ++k) {
        asm volatile("cp.async.wait_group %0;" :: "n"(STG-2));
        __syncthreads();
        int pf = k + STG - 1;
        if (pf < kiters) load_stage(pf % STG, pf * BK);
        CP_COMMIT();

        int slot = k % STG;
        __nv_bfloat16* Asl = As + slot * (BM * LDA_S);
        __nv_bfloat16* BslNN = Bs + slot * (BK * LDB_NN);
        __nv_bfloat16* BslNT = Bs + slot * (BN * LDB_NT);

        // preload kk = 0 fragments into buffer 0
#pragma unroll
        for (int mi = 0; mi < 4; ++mi)
            wmma::load_matrix_sync(fa[0][mi], &Asl[(wm*64 + mi*16)*LDA_S + 0], LDA_S);
        if (!TB) {
#pragma unroll
            for (int ni = 0; ni < 2; ++ni)
                wmma::load_matrix_sync(fbr[0][ni], &BslNN[0*LDB_NN + wn*32 + ni*16], LDB_NN);
        } else {
#pragma unroll
            for (int ni = 0; ni < 2; ++ni)
                wmma::load_matrix_sync(fbc[0][ni], &BslNT[(wn*32 + ni*16)*LDB_NT + 0], LDB_NT);
        }

#pragma unroll
        for (int j = 0; j < 4; ++j) {
            int cur = j & 1, nxt = cur ^ 1;
            if (j < 3) {
                int kk = (j + 1) * 16;
#pragma unroll
                for (int mi = 0; mi < 4; ++mi)
                    wmma::load_matrix_sync(fa[nxt][mi], &Asl[(wm*64 + mi*16)*LDA_S + kk], LDA_S);
                if (!TB) {
#pragma unroll
                    for (int ni = 0; ni < 2; ++ni)
                        wmma::load_matrix_sync(fbr[nxt][ni], &BslNN[kk*LDB_NN + wn*32 + ni*16], LDB_NN);
                } else {
#pragma unroll
                    for (int ni = 0; ni < 2; ++ni)
                        wmma::load_matrix_sync(fbc[nxt][ni], &BslNT[(wn*32 + ni*16)*LDB_NT + kk], LDB_NT);
                }
            }
            if (!TB) {
#pragma unroll
                for (int mi = 0; mi < 4; ++mi)
#pragma unroll
                    for (int ni = 0; ni < 2; ++ni)
                        wmma::mma_sync(acc[mi][ni], fa[cur][mi], fbr[cur][ni], acc[mi][ni]);
            } else {
#pragma unroll
                for (int mi = 0; mi < 4; ++mi)
#pragma unroll
                    for (int ni = 0; ni < 2; ++ni)
                        wmma::mma_sync(acc[mi][ni], fa[cur][mi], fbc[cur][ni], acc[mi][ni]);
            }
        }
    }
    __syncthreads();   // protect smem reuse in epilogue

    // ---------------- epilogue (reuse dsm as staging) ----------------
    float c_res = 0.f, c_out = 0.f;
    if (EPI == 3) { c_res = p.coeffs[p.ci0]; c_out = p.coeffs[p.ci1]; }
    float* ep = (float*)dsm;
    float* eptr = &ep[warp * 16 * EPLD];
#pragma unroll
    for (int mi = 0; mi < 4; ++mi) {
#pragma unroll
        for (int ni = 0; ni < 2; ++ni) {
            wmma::store_matrix_sync(eptr, acc[mi][ni], EPLD, wmma::mem_row_major);
            __syncwarp();
            int r0 = row0 + wm*64 + mi*16;
            int c0 = col0 + wn*32 + ni*16;
#pragma unroll
            for (int e = 0; e < 8; ++e) {
                int i = e*32 + lane;
                int r = i >> 4, c = i & 15;
                float v = eptr[r*EPLD + c];
                long gr = r0 + r, gc = c0 + c;
                long cidx = coff + gr*p.ldc + gc;
                if (EPI == 0) {
                    if (p.bias) v += p.bias[gc];
                    ((__nv_bfloat16*)p.C)[cidx] = __float2bfloat16(v);
                } else if (EPI == 1) {
                    ((float*)p.C)[cidx] = v * p.alpha;
                } else if (EPI == 3) {
                    v += p.bias[gc];
                    ((float*)p.C)[cidx] = c_res * p.resid[gr*p.ldr + gc] + c_out * v;
                } else if (EPI == 4) {
                    v += p.bias[gc];
                    float gl = 0.5f * v * (1.f + erff(v * 0.70710678118654752f));
                    ((__nv_bfloat16*)p.C)[cidx] = __float2bfloat16(gl);
                }
            }
            __syncwarp();
        }
    }
}

// ---------------- host orchestration ----------------
extern "C" void kernel_launch(void* const* d_in, const int* in_sizes, int n_in,
                              void* d_out, int out_size) {
    (void)in_sizes; (void)n_in; (void)out_size;
    const float* rgb    = (const float*)d_in[0];
    const float* irp    = (const float*)d_in[1];
    const float* ln1g   = (const float*)d_in[2];
    const float* ln1b   = (const float*)d_in[3];
    const float* ln2g   = (const float*)d_in[4];
    const float* ln2b   = (const float*)d_in[5];
    const float* Wqkv_v = (const float*)d_in[6];
    const float* bqkv_v = (const float*)d_in[7];
    const float* Wqkv_i = (const float*)d_in[8];
    const float* bqkv_i = (const float*)d_in[9];
    const float* Wo_v   = (const float*)d_in[10];
    const float* bo_v   = (const float*)d_in[11];
    const float* Wo_i   = (const float*)d_in[12];
    const float* bo_i   = (const float*)d_in[13];
    const float* blng   = (const float*)d_in[14];
    const float* blnb   = (const float*)d_in[15];
    const float* W1_v   = (const float*)d_in[16];
    const float* b1_v   = (const float*)d_in[17];
    const float* W2_v   = (const float*)d_in[18];
    const float* b2_v   = (const float*)d_in[19];
    const float* W1_i   = (const float*)d_in[20];
    const float* b1_i   = (const float*)d_in[21];
    const float* W2_i   = (const float*)d_in[22];
    const float* b2_i   = (const float*)d_in[23];
    const float* coef   = (const float*)d_in[24];
    float* out = (float*)d_out;

    __nv_bfloat16 *xln, *wqkv, *wo, *w1, *w2, *qkv, *Pb, *Ob, *attln, *hb;
    float *Sb, *attb;
    cudaGetSymbolAddress((void**)&xln,   g_xln);
    cudaGetSymbolAddress((void**)&wqkv,  g_wqkv);
    cudaGetSymbolAddress((void**)&wo,    g_wo);
    cudaGetSymbolAddress((void**)&w1,    g_w1);
    cudaGetSymbolAddress((void**)&w2,    g_w2);
    cudaGetSymbolAddress((void**)&qkv,   g_qkv);
    cudaGetSymbolAddress((void**)&Sb,    g_Smat);
    cudaGetSymbolAddress((void**)&Pb,    g_Pmat);
    cudaGetSymbolAddress((void**)&Ob,    g_Omat);
    cudaGetSymbolAddress((void**)&attb,  g_att);
    cudaGetSymbolAddress((void**)&attln, g_attln);
    cudaGetSymbolAddress((void**)&hb,    g_hid);

    cudaFuncSetAttribute(gemm_k<0, false>, cudaFuncAttributeMaxDynamicSharedMemorySize, SMEM_NN);
    cudaFuncSetAttribute(gemm_k<3, false>, cudaFuncAttributeMaxDynamicSharedMemorySize, SMEM_NN);
    cudaFuncSetAttribute(gemm_k<4, false>, cudaFuncAttributeMaxDynamicSharedMemorySize, SMEM_NN);
    cudaFuncSetAttribute(gemm_k<1, true>,  cudaFuncAttributeMaxDynamicSharedMemorySize, SMEM_NT);

    // weights -> bf16 (one launch, 8 regions)
    {
        CvtP cp{};
        cp.s[0] = Wqkv_v; cp.d[0] = wqkv;            cp.n[0] = 3145728L;
        cp.s[1] = Wqkv_i; cp.d[1] = wqkv + 3145728L; cp.n[1] = 3145728L;
        cp.s[2] = Wo_v;   cp.d[2] = wo;              cp.n[2] = 1048576L;
        cp.s[3] = Wo_i;   cp.d[3] = wo + 1048576L;   cp.n[3] = 1048576L;
        cp.s[4] = W1_v;   cp.d[4] = w1;              cp.n[4] = 4194304L;
        cp.s[5] = W1_i;   cp.d[5] = w1 + 4194304L;   cp.n[5] = 4194304L;
        cp.s[6] = W2_v;   cp.d[6] = w2;              cp.n[6] = 4194304L;
        cp.s[7] = W2_i;   cp.d[7] = w2 + 4194304L;   cp.n[7] = 4194304L;
        cvt8_k<<<dim3(4096, 8), 256>>>(cp);
    }

    // input LayerNorms (one launch)
    ln2_k<<<dim3(16384, 2), 256>>>(rgb, xln, ln1g, ln1b,
                                   irp, xln + 16777216L, ln2g, ln2b);

    // QKV projections (6 GEMMs, M=16384 N=1024 K=1024) — launch #6 is profiled
    for (int s = 0; s < 2; s++) {
        for (int t = 0; t < 3; t++) {
            GP p{};
            p.A = xln + (long)s * 16777216L;                 p.lda = 1024;
            p.B = wqkv + ((long)s*3 + t) * 1048576L;         p.ldb = 1024;
            p.C = qkv + ((long)s*3 + t) * 16777216L;         p.ldc = 1024;
            p.bias = (s == 0 ? bqkv_v : bqkv_i) + t * 1024;
            p.Hh = 1; p.K = 1024; p.coeffs = coef;
            gemm_k<0, false><<<dim3(8, 128, 1), 256, SMEM_NN>>>(p);
        }
    }

    // scores S = Q @ K^T * scale  (batched over b,h)
    for (int dir = 0; dir < 2; ++dir) {
        int qs = (dir == 0) ? 1 : 0;
        int ks = (dir == 0) ? 0 : 1;
        GP p{};
        p.A = qkv + ((long)qs*3 + 0) * 16777216L;  p.lda = 1024; p.sAb = 262144; p.sAh = 128;
        p.B = qkv + ((long)ks*3 + 1) * 16777216L;  p.ldb = 1024; p.sBb = 262144; p.sBh = 128;
        p.C = Sb + (long)dir * 33554432L;          p.ldc = 256;  p.sCb = 524288; p.sCh = 65536;
        p.Hh = 8; p.K = 128; p.alpha = 0.08838834764831845f; p.coeffs = coef;
        gemm_k<1, true><<<dim3(2, 2, 512), 256, SMEM_NT>>>(p);
    }

    softmax_k<<<32768, 256>>>(Sb, Pb);

    // O = P @ V (batched), merged layout
    for (int dir = 0; dir < 2; ++dir) {
        int ks = (dir == 0) ? 0 : 1;
        GP p{};
        p.A = Pb + (long)dir * 33554432L;          p.lda = 256;  p.sAb = 524288; p.sAh = 65536;
        p.B = qkv + ((long)ks*3 + 2) * 16777216L;  p.ldb = 1024; p.sBb = 262144; p.sBh = 128;
        p.C = Ob + (long)dir * 16777216L;          p.ldc = 1024; p.sCb = 262144; p.sCh = 128;
        p.bias = nullptr; p.Hh = 8; p.K = 256; p.coeffs = coef;
        gemm_k<0, false><<<dim3(1, 2, 512), 256, SMEM_NN>>>(p);
    }

    // output projection + residual
    for (int dir = 0; dir < 2; ++dir) {
        GP p{};
        p.A = Ob + (long)dir * 16777216L;   p.lda = 1024;
        p.B = wo + (long)dir * 1048576L;    p.ldb = 1024;
        p.C = attb + (long)dir * 16777216L; p.ldc = 1024;
        p.bias = (dir == 0) ? bo_v : bo_i;
        p.resid = (dir == 0) ? rgb : irp;   p.ldr = 1024;
        p.coeffs = coef; p.ci0 = 2*dir; p.ci1 = 2*dir + 1;
        p.Hh = 1; p.K = 1024;
        gemm_k<3, false><<<dim3(8, 128, 1), 256, SMEM_NN>>>(p);
    }

    // block LayerNorm (one launch, shared gamma/beta)
    ln2_k<<<dim3(16384, 2), 256>>>(attb, attln, blng, blnb,
                                   attb + 16777216L, attln + 16777216L, blng, blnb);

    // MLP layer 1 + exact GELU (M=16384 N=4096 K=1024)
    for (int s = 0; s < 2; s++) {
        GP p{};
        p.A = attln + (long)s * 16777216L;  p.lda = 1024;
        p.B = w1 + (long)s * 4194304L;      p.ldb = 4096;
        p.C = hb + (long)s * 67108864L;     p.ldc = 4096;
        p.bias = (s == 0) ? b1_v : b1_i;
        p.Hh = 1; p.K = 1024; p.coeffs = coef;
        gemm_k<4, false><<<dim3(32, 128, 1), 256, SMEM_NN>>>(p);
    }

    // MLP layer 2 + final combine -> d_out (M=16384 N=1024 K=4096)
    for (int s = 0; s < 2; s++) {
        GP p{};
        p.A = hb + (long)s * 67108864L;     p.lda = 4096;
        p.B = w2 + (long)s * 4194304L;      p.ldb = 1024;
        p.C = out + (long)s * 16777216L;    p.ldc = 1024;
        p.bias = (s == 0) ? b2_v : b2_i;
        p.resid = attb + (long)s * 16777216L; p.ldr = 1024;
        p.coeffs = coef; p.ci0 = 4 + 2*s; p.ci1 = 5 + 2*s;
        p.Hh = 1; p.K = 4096;
        gemm_k<3, false><<<dim3(8, 128, 1), 256, SMEM_NN>>>(p);
    }
}